// round 10
// baseline (speedup 1.0000x reference)
#include <cuda_runtime.h>
#include <cuda_bf16.h>
#include <cstdint>

#define Bb 8
#define Nn 4096
#define ATTR 16
#define Hh 64
#define STEPS 8
#define CAP 128
#define ROWS (Bb*Nn)            // 32768

typedef unsigned long long ull;

// ------------------------- device scratch -------------------------
__device__ float g_h[ROWS*Hh];       // 8 MB
__device__ float g_ain[ROWS*Hh];     // 8 MB
__device__ float g_aout[ROWS*Hh];    // 8 MB
__device__ int   g_incnt[ROWS];
__device__ int   g_outcnt[ROWS];
__device__ int   g_incol[(size_t)ROWS*CAP];   // 16.8 MB
__device__ int   g_outcol[(size_t)ROWS*CAP];  // 16.8 MB
// pre-split packed bf16x2 weights: [chunk64][n][kk] (kk = k-pair index 0..31)
__device__ uint32_t g_Wbh[3*192*32];
__device__ uint32_t g_Wbl[3*192*32];
__device__ uint32_t g_W2bh[64*32];
__device__ uint32_t g_W2bl[64*32];

// ------------------------- helpers -------------------------
__device__ __forceinline__ float sigmoidf_(float x) { return 1.f / (1.f + __expf(-x)); }
__device__ __forceinline__ float tanhf_(float x) {
    float e = __expf(2.f * x); return 1.f - 2.f / (e + 1.f);
}
// split (a,b) into packed bf16x2 hi + lo residual
__device__ __forceinline__ void bsplit2(float a, float b, uint32_t &hi, uint32_t &lo) {
    __nv_bfloat16 ah = __float2bfloat16_rn(a);
    __nv_bfloat16 bh = __float2bfloat16_rn(b);
    float ar = a - __bfloat162float(ah);
    float br = b - __bfloat162float(bh);
    __nv_bfloat162 h2; h2.x = ah; h2.y = bh;
    __nv_bfloat162 l2 = __floats2bfloat162_rn(ar, br);
    hi = *reinterpret_cast<uint32_t*>(&h2);
    lo = *reinterpret_cast<uint32_t*>(&l2);
}
__device__ __forceinline__ void mma16(float* d, const uint32_t* a, const uint32_t* b) {
    asm volatile(
        "mma.sync.aligned.m16n8k16.row.col.f32.bf16.bf16.f32 "
        "{%0,%1,%2,%3}, {%4,%5,%6,%7}, {%8,%9}, {%0,%1,%2,%3};"
        : "+f"(d[0]), "+f"(d[1]), "+f"(d[2]), "+f"(d[3])
        : "r"(a[0]), "r"(a[1]), "r"(a[2]), "r"(a[3]), "r"(b[0]), "r"(b[1]));
}
__device__ __forceinline__ void add2(ull &acc, ull v) {
    asm("add.rn.f32x2 %0, %0, %1;" : "+l"(acc) : "l"(v));
}

// ------------------------- fused init: h0 + W pack + zero counts -------------------------
__global__ void fused_init(const float* __restrict__ attr,
                           const float* __restrict__ Wi,
                           const float* __restrict__ bi,
                           const float* __restrict__ Wz,
                           const float* __restrict__ Wr,
                           const float* __restrict__ Wh) {
    int bid = blockIdx.x;
    if (bid < 8192) {
        __shared__ float sWiT[ATTR * Hh];
        __shared__ float sAttr[4][ATTR];
        int col = threadIdx.x & 63;
        int r   = threadIdx.x >> 6;
        int row = bid * 4 + r;
        for (int t = threadIdx.x; t < ATTR * Hh; t += 256) {
            int a = t >> 6, c = t & 63;
            sWiT[t] = Wi[c * ATTR + a];
        }
        if (col < ATTR) sAttr[r][col] = attr[(size_t)row * ATTR + col];
        __syncthreads();
        float acc = bi[col];
        #pragma unroll
        for (int a = 0; a < ATTR; a++) acc = fmaf(sAttr[r][a], sWiT[a * 64 + col], acc);
        g_h[(size_t)row * Hh + col] = fmaxf(acc, 0.f);
    } else if (bid < 8272) {
        int e = (bid - 8192) * 256 + threadIdx.x;   // [0, 20480)
        if (e < 18432) {
            int n = e / 96, kkg = e - n * 96;
            int chunk = kkg >> 5, kkc = kkg & 31;
            int k = 2 * kkg;
            float v0, v1;
            if (n < 64)       { v0 = Wz[n * 192 + k];        v1 = Wz[n * 192 + k + 1]; }
            else if (n < 128) { v0 = Wr[(n-64) * 192 + k];   v1 = Wr[(n-64) * 192 + k + 1]; }
            else if (k < 128) { v0 = Wh[(n-128) * 192 + k];  v1 = Wh[(n-128) * 192 + k + 1]; }
            else              { v0 = 0.f; v1 = 0.f; }
            uint32_t hi, lo; bsplit2(v0, v1, hi, lo);
            g_Wbh[chunk * 6144 + n * 32 + kkc] = hi;
            g_Wbl[chunk * 6144 + n * 32 + kkc] = lo;
        } else if (e < 20480) {
            int e2 = e - 18432;
            int n = e2 >> 5, kkc = e2 & 31;
            int k = 2 * kkc;
            float v0 = Wh[n * 192 + 128 + k], v1 = Wh[n * 192 + 128 + k + 1];
            uint32_t hi, lo; bsplit2(v0, v1, hi, lo);
            g_W2bh[n * 32 + kkc] = hi;
            g_W2bl[n * 32 + kkc] = lo;
        }
    } else {
        int i = (bid - 8272) * 256 + threadIdx.x;
        g_incnt[i] = 0; g_outcnt[i] = 0;
    }
}

__global__ void build_csr(const float* __restrict__ adj) {
    int row = blockIdx.x;
    int b   = row >> 12;
    int i   = row & (Nn - 1);
    const float4* a4 = reinterpret_cast<const float4*>(adj + (size_t)row * Nn);
    for (int t = threadIdx.x; t < Nn / 4; t += blockDim.x) {
        float4 v = a4[t];
        int j = 4 * t;
        #pragma unroll
        for (int u = 0; u < 4; u++) {
            float val = (u == 0) ? v.x : (u == 1) ? v.y : (u == 2) ? v.z : v.w;
            if (val != 0.f) {
                int jc = j + u;
                int p = atomicAdd(&g_incnt[row], 1);
                if (p < CAP) g_incol[(size_t)row * CAP + p] = jc;
                int q = atomicAdd(&g_outcnt[(b << 12) + jc], 1);
                if (q < CAP) g_outcol[((size_t)((b << 12) + jc)) * CAP + q] = i;
            }
        }
    }
}

// ------------------------- spmm v2 (best measured) -------------------------
__global__ void __launch_bounds__(256) spmm2() {
    int w    = threadIdx.x >> 5;
    int lane = threadIdx.x & 31;
    int row  = blockIdx.x * 4 + (w >> 1);
    int dir  = w & 1;
    int b    = row >> 12;
    const ull* __restrict__ hb = reinterpret_cast<const ull*>(g_h + ((size_t)(b << 12)) * Hh);
    const int* __restrict__ cl = (dir ? g_outcol : g_incol) + (size_t)row * CAP;
    int cnt = dir ? g_outcnt[row] : g_incnt[row];
    cnt = min(cnt, CAP);
    ull acc = 0;
    int t = 0;
    for (; t + 8 <= cnt; t += 8) {
        int j[8];
        #pragma unroll
        for (int u = 0; u < 8; u++) j[u] = __ldg(cl + t + u);
        ull v[8];
        #pragma unroll
        for (int u = 0; u < 8; u++) v[u] = hb[(size_t)j[u] * 32 + lane];
        #pragma unroll
        for (int u = 0; u < 8; u++) add2(acc, v[u]);
    }
    for (; t < cnt; t++) add2(acc, hb[(size_t)cl[t] * 32 + lane]);
    float* dst = (dir ? g_aout : g_ain) + (size_t)row * Hh;
    *reinterpret_cast<ull*>(dst + 2 * lane) = acc;
}

// ------------------------- GRU: split-bf16 mma, 64-row tiles, 2 CTA/SM -------------------------
#define XPU 36        // X pitch (u32): 32 pairs + 4 pad
#define WPU 20        // W pitch (u32): 16 pairs + 4 pad
#define HPU 68
#define OFF_XH 0                   // 64*36 = 2304
#define OFF_XL 2304
#define OFF_WH 4608                // 192*20 = 3840
#define OFF_WL 8448
#define OFF_H  12288               // 64*68 = 4352
#define OFF_Z  16640
#define OFF_P  20992
#define OFF_B  25344
#define GRUC_U32 25536
#define GRUC_SMEM (GRUC_U32*4)     // 102,144 bytes -> 2 CTAs/SM
#define NTILE3 (ROWS/64)           // 512
#define GRUC_GRID 296

__global__ void __launch_bounds__(256, 2)
gru_c(const float* __restrict__ bz, const float* __restrict__ br,
      const float* __restrict__ bh) {
    extern __shared__ uint32_t smu[];
    uint32_t* sXh = smu + OFF_XH;
    uint32_t* sXl = smu + OFF_XL;
    uint32_t* sWh = smu + OFF_WH;
    uint32_t* sWl = smu + OFF_WL;
    float* sH = reinterpret_cast<float*>(smu + OFF_H);
    float* sZ = reinterpret_cast<float*>(smu + OFF_Z);
    float* sP = reinterpret_cast<float*>(smu + OFF_P);
    float* sB = reinterpret_cast<float*>(smu + OFF_B);

    int tid  = threadIdx.x;
    int wid  = tid >> 5;            // 0..7
    int lane = tid & 31;
    int g    = lane >> 2;
    int t    = lane & 3;
    int rg   = wid & 1;             // row group (2 x 32 rows)
    int cg   = wid >> 1;            // col group (4 x 48 cols)
    int r0   = rg * 32;

    for (int i = tid; i < 192; i += 256)
        sB[i] = (i < 64) ? bz[i] : (i < 128) ? br[i - 64] : bh[i - 128];
    __syncthreads();

    int xrow = tid >> 4;             // 0..15 (rows xrow + 16*i)
    int xq   = tid & 15;             // float4 col index

    for (int tile = blockIdx.x; tile < NTILE3; tile += GRUC_GRID) {
        int tb = tile * 64;
        float acc[2][6][4];
        #pragma unroll
        for (int rs = 0; rs < 2; rs++)
            #pragma unroll
            for (int j = 0; j < 6; j++) {
                acc[rs][j][0] = 0.f; acc[rs][j][1] = 0.f;
                acc[rs][j][2] = 0.f; acc[rs][j][3] = 0.f;
            }

        // prefetch chunk 0 X (a_in)
        float4 vx[4];
        #pragma unroll
        for (int i = 0; i < 4; i++)
            vx[i] = *reinterpret_cast<const float4*>(
                g_ain + (size_t)(tb + xrow + 16 * i) * 64 + xq * 4);

        // ================= phase A: 3 X-chunks x 2 W-subchunks =================
        #pragma unroll 1
        for (int c3 = 0; c3 < 3; c3++) {
            // stage X (protected by trailing sync of previous subchunk)
            #pragma unroll
            for (int i = 0; i < 4; i++) {
                int row = xrow + 16 * i;
                uint32_t h0, l0, h1, l1;
                bsplit2(vx[i].x, vx[i].y, h0, l0);
                bsplit2(vx[i].z, vx[i].w, h1, l1);
                sXh[row * XPU + 2 * xq]     = h0;
                sXh[row * XPU + 2 * xq + 1] = h1;
                sXl[row * XPU + 2 * xq]     = l0;
                sXl[row * XPU + 2 * xq + 1] = l1;
                if (c3 == 2) *reinterpret_cast<float4*>(sH + row * HPU + xq * 4) = vx[i];
            }
            // prefetch next X source
            if (c3 < 2) {
                const float* srcn = (c3 == 0) ? g_aout : g_h;
                #pragma unroll
                for (int i = 0; i < 4; i++)
                    vx[i] = *reinterpret_cast<const float4*>(
                        srcn + (size_t)(tb + xrow + 16 * i) * 64 + xq * 4);
            }
            #pragma unroll 1
            for (int w2 = 0; w2 < 2; w2++) {
                // stage W subchunk (192 rows x 16 pairs)  [w2==0: protected by prev
                // trailing sync; w2==1: by sync after w2==0's MMA]
                for (int f = tid; f < 768; f += 256) {
                    int n = f >> 2, q = f & 3;
                    *reinterpret_cast<uint4*>(sWh + n * WPU + q * 4) =
                        *reinterpret_cast<const uint4*>(g_Wbh + c3 * 6144 + n * 32 + w2 * 16 + q * 4);
                    *reinterpret_cast<uint4*>(sWl + n * WPU + q * 4) =
                        *reinterpret_cast<const uint4*>(g_Wbl + c3 * 6144 + n * 32 + w2 * 16 + q * 4);
                }
                __syncthreads();

                #pragma unroll
                for (int ks = 0; ks < 2; ks++) {
                    int kbx = w2 * 16 + ks * 8 + t;
                    int kbw = ks * 8 + t;
                    uint32_t aH[2][4], aL[2][4];
                    #pragma unroll
                    for (int rs = 0; rs < 2; rs++) {
                        const uint32_t* xr = sXh + (r0 + 16 * rs + g) * XPU;
                        aH[rs][0] = xr[kbx];           aH[rs][2] = xr[kbx + 4];
                        aH[rs][1] = xr[8 * XPU + kbx]; aH[rs][3] = xr[8 * XPU + kbx + 4];
                        const uint32_t* xr2 = sXl + (r0 + 16 * rs + g) * XPU;
                        aL[rs][0] = xr2[kbx];           aL[rs][2] = xr2[kbx + 4];
                        aL[rs][1] = xr2[8 * XPU + kbx]; aL[rs][3] = xr2[8 * XPU + kbx + 4];
                    }
                    uint32_t bw[6][2];
                    #pragma unroll
                    for (int j = 0; j < 6; j++) {
                        const uint32_t* wr = sWh + (cg * 48 + j * 8 + g) * WPU + kbw;
                        bw[j][0] = wr[0]; bw[j][1] = wr[4];
                    }
                    #pragma unroll
                    for (int rs = 0; rs < 2; rs++)
                        #pragma unroll
                        for (int j = 0; j < 6; j++) mma16(acc[rs][j], aH[rs], bw[j]);
                    #pragma unroll
                    for (int rs = 0; rs < 2; rs++)
                        #pragma unroll
                        for (int j = 0; j < 6; j++) mma16(acc[rs][j], aL[rs], bw[j]);
                    #pragma unroll
                    for (int j = 0; j < 6; j++) {
                        const uint32_t* wr = sWl + (cg * 48 + j * 8 + g) * WPU + kbw;
                        bw[j][0] = wr[0]; bw[j][1] = wr[4];
                    }
                    #pragma unroll
                    for (int rs = 0; rs < 2; rs++)
                        #pragma unroll
                        for (int j = 0; j < 6; j++) mma16(acc[rs][j], aH[rs], bw[j]);
                }
                __syncthreads();
            }
        }

        // ================= epilogue 1 =================
        #pragma unroll
        for (int j = 0; j < 6; j++) {
            int cb = cg * 48 + j * 8;
            int c0 = cb + 2 * t;
            #pragma unroll
            for (int rs = 0; rs < 2; rs++) {
                int ra = r0 + 16 * rs + g;
                float* ac = acc[rs][j];
                if (cb < 64) {
                    sZ[ra * HPU + c0]           = sigmoidf_(ac[0] + sB[c0]);
                    sZ[ra * HPU + c0 + 1]       = sigmoidf_(ac[1] + sB[c0 + 1]);
                    sZ[(ra + 8) * HPU + c0]     = sigmoidf_(ac[2] + sB[c0]);
                    sZ[(ra + 8) * HPU + c0 + 1] = sigmoidf_(ac[3] + sB[c0 + 1]);
                } else if (cb < 128) {
                    int cl = c0 - 64;
                    int kk = cl >> 1;
                    float va = sigmoidf_(ac[0] + sB[c0])     * sH[ra * HPU + cl];
                    float vb = sigmoidf_(ac[1] + sB[c0 + 1]) * sH[ra * HPU + cl + 1];
                    uint32_t hi, lo; bsplit2(va, vb, hi, lo);
                    sXh[ra * XPU + kk] = hi; sXl[ra * XPU + kk] = lo;
                    float vc = sigmoidf_(ac[2] + sB[c0])     * sH[(ra + 8) * HPU + cl];
                    float vd = sigmoidf_(ac[3] + sB[c0 + 1]) * sH[(ra + 8) * HPU + cl + 1];
                    bsplit2(vc, vd, hi, lo);
                    sXh[(ra + 8) * XPU + kk] = hi; sXl[(ra + 8) * XPU + kk] = lo;
                } else {
                    int cl = c0 - 128;
                    sP[ra * HPU + cl]           = ac[0] + sB[c0];
                    sP[ra * HPU + cl + 1]       = ac[1] + sB[c0 + 1];
                    sP[(ra + 8) * HPU + cl]     = ac[2] + sB[c0];
                    sP[(ra + 8) * HPU + cl + 1] = ac[3] + sB[c0 + 1];
                }
            }
        }
        // stage BOTH W2 32-k chunks: chunk0 -> sW rows 0..63, chunk1 -> rows 64..127
        for (int f = tid; f < 512; f += 256) {
            int n = f >> 2, q = f & 3;
            int row = n & 63, ch = n >> 6;
            *reinterpret_cast<uint4*>(sWh + n * WPU + q * 4) =
                *reinterpret_cast<const uint4*>(g_W2bh + row * 32 + ch * 16 + q * 4);
            *reinterpret_cast<uint4*>(sWl + n * WPU + q * 4) =
                *reinterpret_cast<const uint4*>(g_W2bl + row * 32 + ch * 16 + q * 4);
        }
        __syncthreads();

        // ================= phase B: hn += rh @ Wh2^T (3-term) =================
        {
            int nn0 = (wid >> 1) * 16;      // col group: 4 x 16
            int r0b = (wid & 1) * 32;       // row group: 2 x 32
            float acc2[2][2][4];
            #pragma unroll
            for (int rs = 0; rs < 2; rs++)
                #pragma unroll
                for (int j = 0; j < 2; j++) {
                    acc2[rs][j][0] = 0.f; acc2[rs][j][1] = 0.f;
                    acc2[rs][j][2] = 0.f; acc2[rs][j][3] = 0.f;
                }
            #pragma unroll
            for (int ks = 0; ks < 4; ks++) {
                int kbx = ks * 8 + t;
                int kbw = (ks & 1) * 8 + t;
                int wro = (ks >> 1) * 64;   // W2 chunk row offset
                uint32_t aH[2][4], aL[2][4];
                #pragma unroll
                for (int rs = 0; rs < 2; rs++) {
                    const uint32_t* xr = sXh + (r0b + 16 * rs + g) * XPU;
                    aH[rs][0] = xr[kbx];           aH[rs][2] = xr[kbx + 4];
                    aH[rs][1] = xr[8 * XPU + kbx]; aH[rs][3] = xr[8 * XPU + kbx + 4];
                    const uint32_t* xr2 = sXl + (r0b + 16 * rs + g) * XPU;
                    aL[rs][0] = xr2[kbx];           aL[rs][2] = xr2[kbx + 4];
                    aL[rs][1] = xr2[8 * XPU + kbx]; aL[rs][3] = xr2[8 * XPU + kbx + 4];
                }
                uint32_t bwh[2][2], bwl[2][2];
                #pragma unroll
                for (int j = 0; j < 2; j++) {
                    const uint32_t* wr = sWh + (wro + nn0 + j * 8 + g) * WPU + kbw;
                    bwh[j][0] = wr[0]; bwh[j][1] = wr[4];
                    const uint32_t* wr2 = sWl + (wro + nn0 + j * 8 + g) * WPU + kbw;
                    bwl[j][0] = wr2[0]; bwl[j][1] = wr2[4];
                }
                #pragma unroll
                for (int rs = 0; rs < 2; rs++)
                    #pragma unroll
                    for (int j = 0; j < 2; j++) mma16(acc2[rs][j], aH[rs], bwh[j]);
                #pragma unroll
                for (int rs = 0; rs < 2; rs++)
                    #pragma unroll
                    for (int j = 0; j < 2; j++) mma16(acc2[rs][j], aL[rs], bwh[j]);
                #pragma unroll
                for (int rs = 0; rs < 2; rs++)
                    #pragma unroll
                    for (int j = 0; j < 2; j++) mma16(acc2[rs][j], aH[rs], bwl[j]);
            }
            #pragma unroll
            for (int j = 0; j < 2; j++) {
                int cl = nn0 + j * 8 + 2 * t;
                #pragma unroll
                for (int rs = 0; rs < 2; rs++) {
                    int ra = r0b + 16 * rs + g;
                    float* ac = acc2[rs][j];
                    sP[ra * HPU + cl]           = tanhf_(ac[0] + sP[ra * HPU + cl]);
                    sP[ra * HPU + cl + 1]       = tanhf_(ac[1] + sP[ra * HPU + cl + 1]);
                    sP[(ra + 8) * HPU + cl]     = tanhf_(ac[2] + sP[(ra + 8) * HPU + cl]);
                    sP[(ra + 8) * HPU + cl + 1] = tanhf_(ac[3] + sP[(ra + 8) * HPU + cl + 1]);
                }
            }
        }
        __syncthreads();

        // ================= final update =================
        {
            int row = tid >> 2;             // 0..63
            int cb4 = (tid & 3) * 16;
            #pragma unroll
            for (int u = 0; u < 4; u++) {
                int c = cb4 + u * 4;
                float4 z4  = *reinterpret_cast<float4*>(sZ + row * HPU + c);
                float4 hn4 = *reinterpret_cast<float4*>(sP + row * HPU + c);
                float4 h4  = *reinterpret_cast<float4*>(sH + row * HPU + c);
                float4 o;
                o.x = h4.x + z4.x * (hn4.x - h4.x);
                o.y = h4.y + z4.y * (hn4.y - h4.y);
                o.z = h4.z + z4.z * (hn4.z - h4.z);
                o.w = h4.w + z4.w * (hn4.w - h4.w);
                *reinterpret_cast<float4*>(g_h + (size_t)(tb + row) * 64 + c) = o;
            }
        }
        __syncthreads();   // protect sX/sH/sW before next tile staging
    }
}

// out[row] = dot(h[row], Wo) + bo
__global__ void out_k(const float* __restrict__ Wo, const float* __restrict__ bo,
                      float* __restrict__ out) {
    int row  = blockIdx.x * 8 + (threadIdx.x >> 5);
    int lane = threadIdx.x & 31;
    const float* hr = g_h + (size_t)row * Hh;
    float a = hr[lane] * Wo[lane] + hr[lane + 32] * Wo[lane + 32];
    #pragma unroll
    for (int o = 16; o; o >>= 1) a += __shfl_xor_sync(0xffffffffu, a, o);
    if (lane == 0) out[row] = a + bo[0];
}

// ------------------------- launch -------------------------
extern "C" void kernel_launch(void* const* d_in, const int* in_sizes, int n_in,
                              void* d_out, int out_size) {
    const float* attr = (const float*)d_in[0];
    const float* adj  = (const float*)d_in[1];
    const float* Wi   = (const float*)d_in[2];
    const float* bi   = (const float*)d_in[3];
    const float* Wz   = (const float*)d_in[4];
    const float* bz   = (const float*)d_in[5];
    const float* Wr   = (const float*)d_in[6];
    const float* br   = (const float*)d_in[7];
    const float* Wh   = (const float*)d_in[8];
    const float* bh   = (const float*)d_in[9];
    const float* Wo   = (const float*)d_in[10];
    const float* bo   = (const float*)d_in[11];
    float* out = (float*)d_out;

    static bool attr_set = false;
    if (!attr_set) {
        cudaFuncSetAttribute(gru_c, cudaFuncAttributeMaxDynamicSharedMemorySize, GRUC_SMEM);
        attr_set = true;
    }

    fused_init<<<8400, 256>>>(attr, Wi, bi, Wz, Wr, Wh);    // launch 1
    build_csr<<<ROWS, 256>>>(adj);                           // launch 2
    for (int s = 0; s < STEPS; s++) {
        spmm2<<<ROWS / 4, 256>>>();                          // launch 3 (step 0)
        gru_c<<<GRUC_GRID, 256, GRUC_SMEM>>>(bz, br, bh);    // launch 4 (step 0) <- ncu
    }
    out_k<<<ROWS / 8, 256>>>(Wo, bo, out);
}

// round 11
// speedup vs baseline: 1.1019x; 1.1019x over previous
#include <cuda_runtime.h>
#include <cuda_bf16.h>
#include <cstdint>

#define Bb 8
#define Nn 4096
#define ATTR 16
#define Hh 64
#define STEPS 8
#define CAP 128
#define ROWS (Bb*Nn)            // 32768

typedef unsigned long long ull;

// ------------------------- device scratch -------------------------
__device__ float g_h[ROWS*Hh];       // 8 MB
__device__ float g_ain[ROWS*Hh];     // 8 MB
__device__ float g_aout[ROWS*Hh];    // 8 MB
__device__ int   g_incnt[ROWS];
__device__ int   g_outcnt[ROWS];
__device__ int   g_incol[(size_t)ROWS*CAP];   // 16.8 MB
__device__ int   g_outcol[(size_t)ROWS*CAP];  // 16.8 MB
// pre-split packed bf16x2 weights: [chunk64][n][kk] (kk = k-pair index 0..31)
__device__ uint32_t g_Wbh[3*192*32];
__device__ uint32_t g_Wbl[3*192*32];
__device__ uint32_t g_W2bh[64*32];
__device__ uint32_t g_W2bl[64*32];

// ------------------------- helpers -------------------------
__device__ __forceinline__ float sigmoidf_(float x) { return 1.f / (1.f + __expf(-x)); }
__device__ __forceinline__ float tanhf_(float x) {
    float e = __expf(2.f * x); return 1.f - 2.f / (e + 1.f);
}
__device__ __forceinline__ void bsplit2(float a, float b, uint32_t &hi, uint32_t &lo) {
    __nv_bfloat16 ah = __float2bfloat16_rn(a);
    __nv_bfloat16 bh = __float2bfloat16_rn(b);
    float ar = a - __bfloat162float(ah);
    float br = b - __bfloat162float(bh);
    __nv_bfloat162 h2; h2.x = ah; h2.y = bh;
    __nv_bfloat162 l2 = __floats2bfloat162_rn(ar, br);
    hi = *reinterpret_cast<uint32_t*>(&h2);
    lo = *reinterpret_cast<uint32_t*>(&l2);
}
__device__ __forceinline__ void mma16(float* d, const uint32_t* a, const uint32_t* b) {
    asm volatile(
        "mma.sync.aligned.m16n8k16.row.col.f32.bf16.bf16.f32 "
        "{%0,%1,%2,%3}, {%4,%5,%6,%7}, {%8,%9}, {%0,%1,%2,%3};"
        : "+f"(d[0]), "+f"(d[1]), "+f"(d[2]), "+f"(d[3])
        : "r"(a[0]), "r"(a[1]), "r"(a[2]), "r"(a[3]), "r"(b[0]), "r"(b[1]));
}
__device__ __forceinline__ void add2(ull &acc, ull v) {
    asm("add.rn.f32x2 %0, %0, %1;" : "+l"(acc) : "l"(v));
}

// ------------------------- fused init: h0 + W pack + zero counts -------------------------
__global__ void fused_init(const float* __restrict__ attr,
                           const float* __restrict__ Wi,
                           const float* __restrict__ bi,
                           const float* __restrict__ Wz,
                           const float* __restrict__ Wr,
                           const float* __restrict__ Wh) {
    int bid = blockIdx.x;
    if (bid < 8192) {
        __shared__ float sWiT[ATTR * Hh];
        __shared__ float sAttr[4][ATTR];
        int col = threadIdx.x & 63;
        int r   = threadIdx.x >> 6;
        int row = bid * 4 + r;
        for (int t = threadIdx.x; t < ATTR * Hh; t += 256) {
            int a = t >> 6, c = t & 63;
            sWiT[t] = Wi[c * ATTR + a];
        }
        if (col < ATTR) sAttr[r][col] = attr[(size_t)row * ATTR + col];
        __syncthreads();
        float acc = bi[col];
        #pragma unroll
        for (int a = 0; a < ATTR; a++) acc = fmaf(sAttr[r][a], sWiT[a * 64 + col], acc);
        g_h[(size_t)row * Hh + col] = fmaxf(acc, 0.f);
    } else if (bid < 8272) {
        int e = (bid - 8192) * 256 + threadIdx.x;   // [0, 20480)
        if (e < 18432) {
            int n = e / 96, kkg = e - n * 96;
            int chunk = kkg >> 5, kkc = kkg & 31;
            int k = 2 * kkg;
            float v0, v1;
            if (n < 64)       { v0 = Wz[n * 192 + k];        v1 = Wz[n * 192 + k + 1]; }
            else if (n < 128) { v0 = Wr[(n-64) * 192 + k];   v1 = Wr[(n-64) * 192 + k + 1]; }
            else if (k < 128) { v0 = Wh[(n-128) * 192 + k];  v1 = Wh[(n-128) * 192 + k + 1]; }
            else              { v0 = 0.f; v1 = 0.f; }
            uint32_t hi, lo; bsplit2(v0, v1, hi, lo);
            g_Wbh[chunk * 6144 + n * 32 + kkc] = hi;
            g_Wbl[chunk * 6144 + n * 32 + kkc] = lo;
        } else if (e < 20480) {
            int e2 = e - 18432;
            int n = e2 >> 5, kkc = e2 & 31;
            int k = 2 * kkc;
            float v0 = Wh[n * 192 + 128 + k], v1 = Wh[n * 192 + 128 + k + 1];
            uint32_t hi, lo; bsplit2(v0, v1, hi, lo);
            g_W2bh[n * 32 + kkc] = hi;
            g_W2bl[n * 32 + kkc] = lo;
        }
    } else {
        int i = (bid - 8272) * 256 + threadIdx.x;
        g_incnt[i] = 0; g_outcnt[i] = 0;
    }
}

__global__ void build_csr(const float* __restrict__ adj) {
    int row = blockIdx.x;
    int b   = row >> 12;
    int i   = row & (Nn - 1);
    const float4* a4 = reinterpret_cast<const float4*>(adj + (size_t)row * Nn);
    for (int t = threadIdx.x; t < Nn / 4; t += blockDim.x) {
        float4 v = a4[t];
        int j = 4 * t;
        #pragma unroll
        for (int u = 0; u < 4; u++) {
            float val = (u == 0) ? v.x : (u == 1) ? v.y : (u == 2) ? v.z : v.w;
            if (val != 0.f) {
                int jc = j + u;
                int p = atomicAdd(&g_incnt[row], 1);
                if (p < CAP) g_incol[(size_t)row * CAP + p] = jc;
                int q = atomicAdd(&g_outcnt[(b << 12) + jc], 1);
                if (q < CAP) g_outcol[((size_t)((b << 12) + jc)) * CAP + q] = i;
            }
        }
    }
}

// ------------------------- spmm v2 (row_base for stream halves) -------------------------
__global__ void __launch_bounds__(256) spmm2(int row_base) {
    int w    = threadIdx.x >> 5;
    int lane = threadIdx.x & 31;
    int row  = row_base + blockIdx.x * 4 + (w >> 1);
    int dir  = w & 1;
    int b    = row >> 12;
    const ull* __restrict__ hb = reinterpret_cast<const ull*>(g_h + ((size_t)(b << 12)) * Hh);
    const int* __restrict__ cl = (dir ? g_outcol : g_incol) + (size_t)row * CAP;
    int cnt = dir ? g_outcnt[row] : g_incnt[row];
    cnt = min(cnt, CAP);
    ull acc = 0;
    int t = 0;
    for (; t + 8 <= cnt; t += 8) {
        int j[8];
        #pragma unroll
        for (int u = 0; u < 8; u++) j[u] = __ldg(cl + t + u);
        ull v[8];
        #pragma unroll
        for (int u = 0; u < 8; u++) v[u] = hb[(size_t)j[u] * 32 + lane];
        #pragma unroll
        for (int u = 0; u < 8; u++) add2(acc, v[u]);
    }
    for (; t < cnt; t++) add2(acc, hb[(size_t)cl[t] * 32 + lane]);
    float* dst = (dir ? g_aout : g_ain) + (size_t)row * Hh;
    *reinterpret_cast<ull*>(dst + 2 * lane) = acc;
}

// ------------------------- GRU via split-bf16 mma (3-term, prefetch) -------------------------
#define XPU 36
#define HPU 68
#define OFF_XH 0
#define OFF_XL 4608
#define OFF_WH 9216
#define OFF_WL 16128
#define OFF_H  23040
#define OFF_Z  31744
#define OFF_P  40448
#define OFF_B  49152
#define GRUB_U32 49344
#define GRUB_SMEM (GRUB_U32*4)   // 197,376

__global__ void __launch_bounds__(512, 1)
gru_b(const float* __restrict__ bz, const float* __restrict__ br,
      const float* __restrict__ bh, int tile_base, int tile_end) {
    extern __shared__ uint32_t smu[];
    uint32_t* sXh = smu + OFF_XH;
    uint32_t* sXl = smu + OFF_XL;
    uint32_t* sWh = smu + OFF_WH;
    uint32_t* sWl = smu + OFF_WL;
    float* sH = reinterpret_cast<float*>(smu + OFF_H);
    float* sZ = reinterpret_cast<float*>(smu + OFF_Z);
    float* sP = reinterpret_cast<float*>(smu + OFF_P);
    float* sB = reinterpret_cast<float*>(smu + OFF_B);

    int tid  = threadIdx.x;
    int wid  = tid >> 5;
    int lane = tid & 31;
    int g    = lane >> 2;
    int t    = lane & 3;
    int rg   = wid & 3;
    int cg   = wid >> 2;
    int r0   = rg * 32;

    for (int i = tid; i < 192; i += 512)
        sB[i] = (i < 64) ? bz[i] : (i < 128) ? br[i - 64] : bh[i - 128];
    __syncthreads();

    int xrow = tid >> 4;
    int xq   = tid & 15;

    for (int tile = tile_base + blockIdx.x; tile < tile_end; tile += gridDim.x) {
        int tb = tile * 128;
        float acc[2][6][4];
        #pragma unroll
        for (int rs = 0; rs < 2; rs++)
            #pragma unroll
            for (int j = 0; j < 6; j++) {
                acc[rs][j][0] = 0.f; acc[rs][j][1] = 0.f;
                acc[rs][j][2] = 0.f; acc[rs][j][3] = 0.f;
            }

        // prefetch chunk 0 X into registers
        float4 vx[4];
        #pragma unroll
        for (int i = 0; i < 4; i++)
            vx[i] = *reinterpret_cast<const float4*>(
                g_ain + (size_t)(tb + xrow + 32 * i) * 64 + xq * 4);

        // ================= phase A: 3 k-chunks of 64 =================
        #pragma unroll 1
        for (int c3 = 0; c3 < 3; c3++) {
            #pragma unroll
            for (int i = 0; i < 4; i++) {
                int row = xrow + 32 * i;
                uint32_t h0, l0, h1, l1;
                bsplit2(vx[i].x, vx[i].y, h0, l0);
                bsplit2(vx[i].z, vx[i].w, h1, l1);
                sXh[row * XPU + 2 * xq]     = h0;
                sXh[row * XPU + 2 * xq + 1] = h1;
                sXl[row * XPU + 2 * xq]     = l0;
                sXl[row * XPU + 2 * xq + 1] = l1;
                if (c3 == 2) *reinterpret_cast<float4*>(sH + row * HPU + xq * 4) = vx[i];
            }
            for (int f = tid; f < 1536; f += 512) {
                int n = f >> 3, q = f & 7;
                *reinterpret_cast<uint4*>(sWh + n * XPU + q * 4) =
                    *reinterpret_cast<const uint4*>(g_Wbh + c3 * 6144 + n * 32 + q * 4);
                *reinterpret_cast<uint4*>(sWl + n * XPU + q * 4) =
                    *reinterpret_cast<const uint4*>(g_Wbl + c3 * 6144 + n * 32 + q * 4);
            }
            __syncthreads();

            if (c3 < 2) {
                const float* srcn = (c3 == 0) ? g_aout : g_h;
                #pragma unroll
                for (int i = 0; i < 4; i++)
                    vx[i] = *reinterpret_cast<const float4*>(
                        srcn + (size_t)(tb + xrow + 32 * i) * 64 + xq * 4);
            }

            #pragma unroll 2
            for (int ks = 0; ks < 4; ks++) {
                int kb = ks * 8 + t;
                uint32_t aH[2][4], aL[2][4];
                #pragma unroll
                for (int rs = 0; rs < 2; rs++) {
                    const uint32_t* xr = sXh + (r0 + 16 * rs + g) * XPU;
                    aH[rs][0] = xr[kb];           aH[rs][2] = xr[kb + 4];
                    aH[rs][1] = xr[8 * XPU + kb]; aH[rs][3] = xr[8 * XPU + kb + 4];
                    const uint32_t* xr2 = sXl + (r0 + 16 * rs + g) * XPU;
                    aL[rs][0] = xr2[kb];           aL[rs][2] = xr2[kb + 4];
                    aL[rs][1] = xr2[8 * XPU + kb]; aL[rs][3] = xr2[8 * XPU + kb + 4];
                }
                uint32_t bw[6][2];
                #pragma unroll
                for (int j = 0; j < 6; j++) {
                    const uint32_t* wr = sWh + (cg * 48 + j * 8 + g) * XPU;
                    bw[j][0] = wr[kb]; bw[j][1] = wr[kb + 4];
                }
                #pragma unroll
                for (int rs = 0; rs < 2; rs++)
                    #pragma unroll
                    for (int j = 0; j < 6; j++) mma16(acc[rs][j], aH[rs], bw[j]);
                #pragma unroll
                for (int rs = 0; rs < 2; rs++)
                    #pragma unroll
                    for (int j = 0; j < 6; j++) mma16(acc[rs][j], aL[rs], bw[j]);
                #pragma unroll
                for (int j = 0; j < 6; j++) {
                    const uint32_t* wr = sWl + (cg * 48 + j * 8 + g) * XPU;
                    bw[j][0] = wr[kb]; bw[j][1] = wr[kb + 4];
                }
                #pragma unroll
                for (int rs = 0; rs < 2; rs++)
                    #pragma unroll
                    for (int j = 0; j < 6; j++) mma16(acc[rs][j], aH[rs], bw[j]);
            }
            __syncthreads();
        }

        // ================= epilogue 1 =================
        #pragma unroll
        for (int j = 0; j < 6; j++) {
            int cb = cg * 48 + j * 8;
            int c0 = cb + 2 * t;
            #pragma unroll
            for (int rs = 0; rs < 2; rs++) {
                int ra = r0 + 16 * rs + g;
                float* ac = acc[rs][j];
                if (cb < 64) {
                    sZ[ra * HPU + c0]           = sigmoidf_(ac[0] + sB[c0]);
                    sZ[ra * HPU + c0 + 1]       = sigmoidf_(ac[1] + sB[c0 + 1]);
                    sZ[(ra + 8) * HPU + c0]     = sigmoidf_(ac[2] + sB[c0]);
                    sZ[(ra + 8) * HPU + c0 + 1] = sigmoidf_(ac[3] + sB[c0 + 1]);
                } else if (cb < 128) {
                    int cl = c0 - 64;
                    int kk = cl >> 1;
                    float va = sigmoidf_(ac[0] + sB[c0])     * sH[ra * HPU + cl];
                    float vb = sigmoidf_(ac[1] + sB[c0 + 1]) * sH[ra * HPU + cl + 1];
                    uint32_t hi, lo; bsplit2(va, vb, hi, lo);
                    sXh[ra * XPU + kk] = hi; sXl[ra * XPU + kk] = lo;
                    float vc = sigmoidf_(ac[2] + sB[c0])     * sH[(ra + 8) * HPU + cl];
                    float vd = sigmoidf_(ac[3] + sB[c0 + 1]) * sH[(ra + 8) * HPU + cl + 1];
                    bsplit2(vc, vd, hi, lo);
                    sXh[(ra + 8) * XPU + kk] = hi; sXl[(ra + 8) * XPU + kk] = lo;
                } else {
                    int cl = c0 - 128;
                    sP[ra * HPU + cl]           = ac[0] + sB[c0];
                    sP[ra * HPU + cl + 1]       = ac[1] + sB[c0 + 1];
                    sP[(ra + 8) * HPU + cl]     = ac[2] + sB[c0];
                    sP[(ra + 8) * HPU + cl + 1] = ac[3] + sB[c0 + 1];
                }
            }
        }
        {
            int n = tid >> 3, q = tid & 7;
            *reinterpret_cast<uint4*>(sWh + n * XPU + q * 4) =
                *reinterpret_cast<const uint4*>(g_W2bh + n * 32 + q * 4);
            *reinterpret_cast<uint4*>(sWl + n * XPU + q * 4) =
                *reinterpret_cast<const uint4*>(g_W2bl + n * 32 + q * 4);
        }
        __syncthreads();

        // ================= phase B: hn += rh @ Wh2^T (3-term) =================
        {
            int nn0 = (wid >> 2) * 16;
            int r0b = (wid & 3) * 32;
            float acc2[2][2][4];
            #pragma unroll
            for (int rs = 0; rs < 2; rs++)
                #pragma unroll
                for (int j = 0; j < 2; j++) {
                    acc2[rs][j][0] = 0.f; acc2[rs][j][1] = 0.f;
                    acc2[rs][j][2] = 0.f; acc2[rs][j][3] = 0.f;
                }
            #pragma unroll
            for (int ks = 0; ks < 4; ks++) {
                int kb = ks * 8 + t;
                uint32_t aH[2][4], aL[2][4];
                #pragma unroll
                for (int rs = 0; rs < 2; rs++) {
                    const uint32_t* xr = sXh + (r0b + 16 * rs + g) * XPU;
                    aH[rs][0] = xr[kb];           aH[rs][2] = xr[kb + 4];
                    aH[rs][1] = xr[8 * XPU + kb]; aH[rs][3] = xr[8 * XPU + kb + 4];
                    const uint32_t* xr2 = sXl + (r0b + 16 * rs + g) * XPU;
                    aL[rs][0] = xr2[kb];           aL[rs][2] = xr2[kb + 4];
                    aL[rs][1] = xr2[8 * XPU + kb]; aL[rs][3] = xr2[8 * XPU + kb + 4];
                }
                uint32_t bwh[2][2], bwl[2][2];
                #pragma unroll
                for (int j = 0; j < 2; j++) {
                    const uint32_t* wr = sWh + (nn0 + j * 8 + g) * XPU;
                    bwh[j][0] = wr[kb]; bwh[j][1] = wr[kb + 4];
                    const uint32_t* wr2 = sWl + (nn0 + j * 8 + g) * XPU;
                    bwl[j][0] = wr2[kb]; bwl[j][1] = wr2[kb + 4];
                }
                #pragma unroll
                for (int rs = 0; rs < 2; rs++)
                    #pragma unroll
                    for (int j = 0; j < 2; j++) mma16(acc2[rs][j], aH[rs], bwh[j]);
                #pragma unroll
                for (int rs = 0; rs < 2; rs++)
                    #pragma unroll
                    for (int j = 0; j < 2; j++) mma16(acc2[rs][j], aL[rs], bwh[j]);
                #pragma unroll
                for (int rs = 0; rs < 2; rs++)
                    #pragma unroll
                    for (int j = 0; j < 2; j++) mma16(acc2[rs][j], aH[rs], bwl[j]);
            }
            #pragma unroll
            for (int j = 0; j < 2; j++) {
                int cl = nn0 + j * 8 + 2 * t;
                #pragma unroll
                for (int rs = 0; rs < 2; rs++) {
                    int ra = r0b + 16 * rs + g;
                    float* ac = acc2[rs][j];
                    sP[ra * HPU + cl]           = tanhf_(ac[0] + sP[ra * HPU + cl]);
                    sP[ra * HPU + cl + 1]       = tanhf_(ac[1] + sP[ra * HPU + cl + 1]);
                    sP[(ra + 8) * HPU + cl]     = tanhf_(ac[2] + sP[(ra + 8) * HPU + cl]);
                    sP[(ra + 8) * HPU + cl + 1] = tanhf_(ac[3] + sP[(ra + 8) * HPU + cl + 1]);
                }
            }
        }
        __syncthreads();

        // ================= final update =================
        {
            int row = tid >> 2;
            int cb4 = (tid & 3) * 16;
            #pragma unroll
            for (int u = 0; u < 4; u++) {
                int c = cb4 + u * 4;
                float4 z4  = *reinterpret_cast<float4*>(sZ + row * HPU + c);
                float4 hn4 = *reinterpret_cast<float4*>(sP + row * HPU + c);
                float4 h4  = *reinterpret_cast<float4*>(sH + row * HPU + c);
                float4 o;
                o.x = h4.x + z4.x * (hn4.x - h4.x);
                o.y = h4.y + z4.y * (hn4.y - h4.y);
                o.z = h4.z + z4.z * (hn4.z - h4.z);
                o.w = h4.w + z4.w * (hn4.w - h4.w);
                *reinterpret_cast<float4*>(g_h + (size_t)(tb + row) * 64 + c) = o;
            }
        }
        __syncthreads();
    }
}

// out[row] = dot(h[row], Wo) + bo
__global__ void out_k(const float* __restrict__ Wo, const float* __restrict__ bo,
                      float* __restrict__ out) {
    int row  = blockIdx.x * 8 + (threadIdx.x >> 5);
    int lane = threadIdx.x & 31;
    const float* hr = g_h + (size_t)row * Hh;
    float a = hr[lane] * Wo[lane] + hr[lane + 32] * Wo[lane + 32];
    #pragma unroll
    for (int o = 16; o; o >>= 1) a += __shfl_xor_sync(0xffffffffu, a, o);
    if (lane == 0) out[row] = a + bo[0];
}

// ------------------------- launch: two-stream batch-half pipeline -------------------------
extern "C" void kernel_launch(void* const* d_in, const int* in_sizes, int n_in,
                              void* d_out, int out_size) {
    const float* attr = (const float*)d_in[0];
    const float* adj  = (const float*)d_in[1];
    const float* Wi   = (const float*)d_in[2];
    const float* bi   = (const float*)d_in[3];
    const float* Wz   = (const float*)d_in[4];
    const float* bz   = (const float*)d_in[5];
    const float* Wr   = (const float*)d_in[6];
    const float* br   = (const float*)d_in[7];
    const float* Wh   = (const float*)d_in[8];
    const float* bh   = (const float*)d_in[9];
    const float* Wo   = (const float*)d_in[10];
    const float* bo   = (const float*)d_in[11];
    float* out = (float*)d_out;

    static bool init_done = false;
    static cudaStream_t s1, s2;
    static cudaEvent_t ev0, ev1, ev2;
    if (!init_done) {
        cudaFuncSetAttribute(gru_b, cudaFuncAttributeMaxDynamicSharedMemorySize, GRUB_SMEM);
        cudaStreamCreateWithFlags(&s1, cudaStreamNonBlocking);
        cudaStreamCreateWithFlags(&s2, cudaStreamNonBlocking);
        cudaEventCreateWithFlags(&ev0, cudaEventDisableTiming);
        cudaEventCreateWithFlags(&ev1, cudaEventDisableTiming);
        cudaEventCreateWithFlags(&ev2, cudaEventDisableTiming);
        init_done = true;
    }

    // prologue on the capture (legacy) stream
    fused_init<<<8400, 256>>>(attr, Wi, bi, Wz, Wr, Wh);
    build_csr<<<ROWS, 256>>>(adj);

    // fork
    cudaEventRecord(ev0, 0);
    cudaStreamWaitEvent(s1, ev0, 0);
    cudaStreamWaitEvent(s2, ev0, 0);

    // half 0: rows [0, 16384) = batches 0-3 -> s1
    // half 1: rows [16384, 32768) = batches 4-7 -> s2
    for (int s = 0; s < STEPS; s++) {
        spmm2<<<4096, 256, 0, s1>>>(0);
        gru_b<<<128, 512, GRUB_SMEM, s1>>>(bz, br, bh, 0, 128);
        spmm2<<<4096, 256, 0, s2>>>(16384);
        gru_b<<<128, 512, GRUB_SMEM, s2>>>(bz, br, bh, 128, 256);
    }

    // join
    cudaEventRecord(ev1, s1);
    cudaEventRecord(ev2, s2);
    cudaStreamWaitEvent(0, ev1, 0);
    cudaStreamWaitEvent(0, ev2, 0);

    out_k<<<ROWS / 8, 256>>>(Wo, bo, out);
}